// round 3
// baseline (speedup 1.0000x reference)
#include <cuda_runtime.h>
#include <cuda_fp16.h>
#include <cstdint>
#include <cstddef>

// Problem dims
#define TOKENS 32768
#define EDIM   1024
#define FDIM   1024

// GEMM tiling
#define BM 128
#define BN 128
#define BK 32
#define STAGES 4
#define KITERS (FDIM / BK)        // 32
#define GTHREADS 256              // 8 warps: 2 (M) x 4 (N)

// smem: padded row stride 40 halves (80B) -> conflict-free ldmatrix
#define SK 40
#define TILE_HALVES (128 * SK)                    // per operand per stage
#define STAGE_HALVES (2 * TILE_HALVES)            // A then B
#define GEMM_SMEM_BYTES (STAGES * STAGE_HALVES * 2)   // 81920 B

// ---------------- scratch (static device globals: allowed) ----------------
__device__ __half g_Hh[(size_t)TOKENS * FDIM];    // 64 MB
__device__ __half g_W2h[EDIM * FDIM];             // 2 MB

// ---------------- helpers ----------------
__device__ __forceinline__ uint32_t smem_u32(const void* p) {
    return (uint32_t)__cvta_generic_to_shared(p);
}
__device__ __forceinline__ void cp16(uint32_t dst, const __half* src) {
    asm volatile("cp.async.cg.shared.global [%0], [%1], 16;"
                 :: "r"(dst), "l"(__cvta_generic_to_global((const void*)src))
                 : "memory");
}
__device__ __forceinline__ void ldsm_x4(uint32_t* r, uint32_t addr) {
    asm volatile("ldmatrix.sync.aligned.m8n8.x4.shared.b16 {%0,%1,%2,%3}, [%4];"
                 : "=r"(r[0]), "=r"(r[1]), "=r"(r[2]), "=r"(r[3]) : "r"(addr));
}
__device__ __forceinline__ void mma16816(float* c, const uint32_t* a, uint32_t b0, uint32_t b1) {
    asm volatile(
        "mma.sync.aligned.m16n8k16.row.col.f32.f16.f16.f32 "
        "{%0,%1,%2,%3}, {%4,%5,%6,%7}, {%8,%9}, {%0,%1,%2,%3};"
        : "+f"(c[0]), "+f"(c[1]), "+f"(c[2]), "+f"(c[3])
        : "r"(a[0]), "r"(a[1]), "r"(a[2]), "r"(a[3]), "r"(b0), "r"(b1));
}

// ---------------- kernel 1: W2 -> fp16 ----------------
__global__ void w2h_kernel(const float* __restrict__ W2) {
    int i = blockIdx.x * 1024 + threadIdx.x;
    g_W2h[i] = __float2half_rn(W2[i]);
}

// ---------------- kernel 2: H = relu(cos(x[:,:10]) @ W1^T + b1) -> fp16 ----------------
__global__ void __launch_bounds__(256) h_kernel(const float* __restrict__ x,
                                                const float* __restrict__ W1,
                                                const float* __restrict__ b1) {
    __shared__ float sW1T[10 * 1024];   // [q][f]
    __shared__ float sb1[1024];
    const int tid = threadIdx.x;
    for (int i = tid; i < 10 * 1024; i += 256) {
        int f = i / 10, q = i % 10;
        sW1T[q * 1024 + f] = W1[i];
    }
    for (int i = tid; i < 1024; i += 256) sb1[i] = b1[i];
    __syncthreads();

    const int w = tid >> 5, l = tid & 31;
    for (int t = 0; t < 4; ++t) {
        const int token = blockIdx.x * 32 + w * 4 + t;
        float zv = 0.0f;
        if (l < 10) zv = cosf(x[(size_t)token * EDIM + l]);
        float z[10];
        #pragma unroll
        for (int q = 0; q < 10; ++q) z[q] = __shfl_sync(0xffffffffu, zv, q);
        __half* dst = &g_Hh[(size_t)token * FDIM];
        #pragma unroll 4
        for (int f = l; f < FDIM; f += 32) {
            float acc = sb1[f];
            #pragma unroll
            for (int q = 0; q < 10; ++q) acc = fmaf(z[q], sW1T[q * 1024 + f], acc);
            dst[f] = __float2half_rn(fmaxf(acc, 0.0f));
        }
    }
}

// ---------------- kernel 3: out = H @ W2^T + b2 (mma.sync pipeline) ----------------
__device__ __forceinline__ void load_stage(__half* sm, int stage, int m_base,
                                           int n_base, int k0, int tid) {
    __half* sA = sm + stage * STAGE_HALVES;
    __half* sB = sA + TILE_HALVES;
    // 512 16B chunks each for A and B; 256 threads x 2 chunks
    #pragma unroll
    for (int i = 0; i < 2; ++i) {
        int ch = tid + i * 256;
        int r = ch >> 2, c = ch & 3;
        uint32_t so = smem_u32(sA + r * SK + c * 8);
        cp16(so, &g_Hh[(size_t)(m_base + r) * FDIM + k0 + c * 8]);
    }
    #pragma unroll
    for (int i = 0; i < 2; ++i) {
        int ch = tid + i * 256;
        int r = ch >> 2, c = ch & 3;
        uint32_t so = smem_u32(sB + r * SK + c * 8);
        cp16(so, &g_W2h[(size_t)(n_base + r) * FDIM + k0 + c * 8]);
    }
}

__global__ void __launch_bounds__(GTHREADS, 2)
gemm_kernel(const float* __restrict__ b2, float* __restrict__ out) {
    extern __shared__ __half sm[];
    const int tid = threadIdx.x;
    const int wid = tid >> 5;
    const int lane = tid & 31;
    const int warp_m = wid & 1;        // 0..1  (64 rows each)
    const int warp_n = wid >> 1;       // 0..3  (32 cols each)
    const int m_base = blockIdx.y * BM;
    const int n_base = blockIdx.x * BN;

    float acc[4][4][4];                // [mt][n8][4]
    #pragma unroll
    for (int i = 0; i < 4; ++i)
        #pragma unroll
        for (int j = 0; j < 4; ++j)
            #pragma unroll
            for (int k = 0; k < 4; ++k) acc[i][j][k] = 0.0f;

    // prologue: fill STAGES-1 stages
    #pragma unroll
    for (int s = 0; s < STAGES - 1; ++s) {
        load_stage(sm, s, m_base, n_base, s * BK, tid);
        asm volatile("cp.async.commit_group;" ::: "memory");
    }

    // ldmatrix lane addressing: row = lane%16, chunk = lane/16
    const int lrow = lane & 15;
    const int lch  = lane >> 4;

    for (int it = 0; it < KITERS; ++it) {
        asm volatile("cp.async.wait_group %0;" :: "n"(STAGES - 2) : "memory");
        __syncthreads();

        // issue loads for stage it+STAGES-1 (overwrites buf read in iter it-1;
        // safe: all threads passed syncthreads after finishing those ldmatrix)
        if (it + STAGES - 1 < KITERS) {
            load_stage(sm, (it + STAGES - 1) % STAGES, m_base, n_base,
                       (it + STAGES - 1) * BK, tid);
        }
        asm volatile("cp.async.commit_group;" ::: "memory");

        __half* sA = sm + (it % STAGES) * STAGE_HALVES;
        __half* sB = sA + TILE_HALVES;

        #pragma unroll
        for (int kh = 0; kh < 2; ++kh) {
            uint32_t a[4][4];
            #pragma unroll
            for (int mt = 0; mt < 4; ++mt) {
                uint32_t ad = smem_u32(sA + (warp_m * 64 + mt * 16 + lrow) * SK
                                          + kh * 16 + lch * 8);
                ldsm_x4(a[mt], ad);
            }
            uint32_t b[2][4];
            #pragma unroll
            for (int nt = 0; nt < 2; ++nt) {
                uint32_t bd = smem_u32(sB + (warp_n * 32 + nt * 16 + lrow) * SK
                                          + kh * 16 + lch * 8);
                ldsm_x4(b[nt], bd);
            }
            #pragma unroll
            for (int mt = 0; mt < 4; ++mt) {
                #pragma unroll
                for (int nt = 0; nt < 2; ++nt) {
                    // n8 block 2*nt   -> regs {b0, b2}; 2*nt+1 -> {b1, b3}
                    mma16816(acc[mt][2 * nt + 0], a[mt], b[nt][0], b[nt][2]);
                    mma16816(acc[mt][2 * nt + 1], a[mt], b[nt][1], b[nt][3]);
                }
            }
        }
    }

    // epilogue: out[token][col] = acc + b2[col]
    const int col0 = n_base + warp_n * 32;
    float bb[4][2];
    #pragma unroll
    for (int n8 = 0; n8 < 4; ++n8) {
        int c = col0 + n8 * 8 + (lane & 3) * 2;
        bb[n8][0] = __ldg(&b2[c]);
        bb[n8][1] = __ldg(&b2[c + 1]);
    }
    #pragma unroll
    for (int mt = 0; mt < 4; ++mt) {
        const int row0 = m_base + warp_m * 64 + mt * 16 + (lane >> 2);
        #pragma unroll
        for (int n8 = 0; n8 < 4; ++n8) {
            const int c = col0 + n8 * 8 + (lane & 3) * 2;
            float2 v0 = make_float2(acc[mt][n8][0] + bb[n8][0],
                                    acc[mt][n8][1] + bb[n8][1]);
            float2 v1 = make_float2(acc[mt][n8][2] + bb[n8][0],
                                    acc[mt][n8][3] + bb[n8][1]);
            *reinterpret_cast<float2*>(out + (size_t)row0 * EDIM + c) = v0;
            *reinterpret_cast<float2*>(out + (size_t)(row0 + 8) * EDIM + c) = v1;
        }
    }
}

// ---------------- launch ----------------
extern "C" void kernel_launch(void* const* d_in, const int* in_sizes, int n_in,
                              void* d_out, int out_size) {
    const float *x = nullptr, *W1 = nullptr, *b1 = nullptr, *W2 = nullptr, *b2 = nullptr;
    for (int i = 0; i < n_in; ++i) {
        const float* p = (const float*)d_in[i];
        int s = in_sizes[i];
        if (s == TOKENS * EDIM)      x = p;
        else if (s == FDIM * 10)     W1 = p;
        else if (s == EDIM * FDIM)   W2 = p;
        else if (s == 1024) {
            if (!b1) b1 = p; else b2 = p;
        }
        // s == 10 -> rz_theta: phases drop out of <Z>, unused
    }
    float* out = (float*)d_out;

    w2h_kernel<<<1024, 1024>>>(W2);
    h_kernel<<<1024, 256>>>(x, W1, b1);

    cudaFuncSetAttribute(gemm_kernel, cudaFuncAttributeMaxDynamicSharedMemorySize,
                         GEMM_SMEM_BYTES);
    dim3 grid(EDIM / BN, TOKENS / BM);   // (8, 256); N-tiles innermost for A reuse
    gemm_kernel<<<grid, GTHREADS, GEMM_SMEM_BYTES>>>(b2, out);
}

// round 5
// speedup vs baseline: 1.0801x; 1.0801x over previous
#include <cuda_runtime.h>
#include <cuda_fp16.h>
#include <cstdint>
#include <cstddef>

// Problem dims
#define TOKENS 32768
#define EDIM   1024
#define FDIM   1024

// GEMM tiling
#define BM 128
#define BN 128
#define BK 64
#define STAGES 3
#define KITERS (FDIM / BK)        // 16
#define GTHREADS 256              // 8 warps: 2 (M) x 4 (N)

// smem: padded row stride 72 halves (144B) -> conflict-free ldmatrix
#define SK 72
#define TILE_HALVES (128 * SK)                    // per operand per stage
#define STAGE_HALVES (2 * TILE_HALVES)            // A then B
#define GEMM_SMEM_BYTES (STAGES * STAGE_HALVES * 2)   // 110592 B

// ---------------- scratch (static device globals: allowed) ----------------
__device__ __half g_Hh[(size_t)TOKENS * FDIM];    // 64 MB
__device__ __half g_W2h[EDIM * FDIM];             // 2 MB

// ---------------- helpers ----------------
__device__ __forceinline__ uint32_t smem_u32(const void* p) {
    return (uint32_t)__cvta_generic_to_shared(p);
}
__device__ __forceinline__ void cp16(uint32_t dst, const __half* src) {
    asm volatile("cp.async.cg.shared.global [%0], [%1], 16;"
                 :: "r"(dst), "l"(__cvta_generic_to_global((const void*)src))
                 : "memory");
}
__device__ __forceinline__ void ldsm_x4(uint32_t* r, uint32_t addr) {
    asm volatile("ldmatrix.sync.aligned.m8n8.x4.shared.b16 {%0,%1,%2,%3}, [%4];"
                 : "=r"(r[0]), "=r"(r[1]), "=r"(r[2]), "=r"(r[3]) : "r"(addr));
}
__device__ __forceinline__ void mma16816(float* c, const uint32_t* a, uint32_t b0, uint32_t b1) {
    asm volatile(
        "mma.sync.aligned.m16n8k16.row.col.f32.f16.f16.f32 "
        "{%0,%1,%2,%3}, {%4,%5,%6,%7}, {%8,%9}, {%0,%1,%2,%3};"
        : "+f"(c[0]), "+f"(c[1]), "+f"(c[2]), "+f"(c[3])
        : "r"(a[0]), "r"(a[1]), "r"(a[2]), "r"(a[3]), "r"(b0), "r"(b1));
}

// ---------------- kernel 1: prep = {H build} U {W2 convert} ----------------
// blocks [0, 1024): H for 32 tokens each.  blocks [1024, 1280): W2 fp32->fp16, 4096 elems each.
__global__ void __launch_bounds__(256) prep_kernel(const float* __restrict__ x,
                                                   const float* __restrict__ W1,
                                                   const float* __restrict__ b1,
                                                   const float* __restrict__ W2) {
    if (blockIdx.x >= 1024) {
        int base = (blockIdx.x - 1024) * 4096 + threadIdx.x;
        #pragma unroll
        for (int i = 0; i < 16; ++i) {
            int idx = base + i * 256;
            g_W2h[idx] = __float2half_rn(W2[idx]);
        }
        return;
    }
    __shared__ float sW1T[10 * 1024];   // [q][f]
    __shared__ float sb1[1024];
    const int tid = threadIdx.x;
    for (int i = tid; i < 10 * 1024; i += 256) {
        int f = i / 10, q = i % 10;
        sW1T[q * 1024 + f] = W1[i];
    }
    for (int i = tid; i < 1024; i += 256) sb1[i] = b1[i];
    __syncthreads();

    const int w = tid >> 5, l = tid & 31;
    for (int t = 0; t < 4; ++t) {
        const int token = blockIdx.x * 32 + w * 4 + t;
        float zv = 0.0f;
        if (l < 10) zv = cosf(x[(size_t)token * EDIM + l]);
        float z[10];
        #pragma unroll
        for (int q = 0; q < 10; ++q) z[q] = __shfl_sync(0xffffffffu, zv, q);
        __half* dst = &g_Hh[(size_t)token * FDIM];
        #pragma unroll 4
        for (int f = l; f < FDIM; f += 32) {
            float acc = sb1[f];
            #pragma unroll
            for (int q = 0; q < 10; ++q) acc = fmaf(z[q], sW1T[q * 1024 + f], acc);
            dst[f] = __float2half_rn(fmaxf(acc, 0.0f));
        }
    }
}

// ---------------- kernel 2: out = H @ W2^T + b2 (mma.sync pipeline) ----------------
__device__ __forceinline__ void load_stage(__half* sm, int stage, int m_base,
                                           int n_base, int k0, int tid) {
    __half* sA = sm + stage * STAGE_HALVES;
    __half* sB = sA + TILE_HALVES;
    // 1024 16B chunks each for A and B; 256 threads x 4 chunks each
    #pragma unroll
    for (int i = 0; i < 4; ++i) {
        int ch = tid + i * 256;
        int r = ch >> 3, c = ch & 7;
        uint32_t so = smem_u32(sA + r * SK + c * 8);
        cp16(so, &g_Hh[(size_t)(m_base + r) * FDIM + k0 + c * 8]);
    }
    #pragma unroll
    for (int i = 0; i < 4; ++i) {
        int ch = tid + i * 256;
        int r = ch >> 3, c = ch & 7;
        uint32_t so = smem_u32(sB + r * SK + c * 8);
        cp16(so, &g_W2h[(size_t)(n_base + r) * FDIM + k0 + c * 8]);
    }
}

__global__ void __launch_bounds__(GTHREADS, 2)
gemm_kernel(const float* __restrict__ b2, float* __restrict__ out) {
    extern __shared__ __half sm[];
    const int tid = threadIdx.x;
    const int wid = tid >> 5;
    const int lane = tid & 31;
    const int warp_m = wid & 1;        // 0..1  (64 rows each)
    const int warp_n = wid >> 1;       // 0..3  (32 cols each)
    const int m_base = blockIdx.y * BM;
    const int n_base = blockIdx.x * BN;

    float acc[4][4][4];                // [mt][n8][4]
    #pragma unroll
    for (int i = 0; i < 4; ++i)
        #pragma unroll
        for (int j = 0; j < 4; ++j)
            #pragma unroll
            for (int k = 0; k < 4; ++k) acc[i][j][k] = 0.0f;

    // prologue: fill STAGES-1 stages
    #pragma unroll
    for (int s = 0; s < STAGES - 1; ++s) {
        load_stage(sm, s, m_base, n_base, s * BK, tid);
        asm volatile("cp.async.commit_group;" ::: "memory");
    }

    // ldmatrix lane addressing: row = lane%16, chunk = lane/16
    const int lrow = lane & 15;
    const int lch  = lane >> 4;

    for (int it = 0; it < KITERS; ++it) {
        asm volatile("cp.async.wait_group %0;" :: "n"(STAGES - 2) : "memory");
        __syncthreads();

        // issue loads for stage it+STAGES-1 (overwrites buf read in iter it-1;
        // safe: all threads passed syncthreads after finishing those ldmatrix)
        if (it + STAGES - 1 < KITERS) {
            load_stage(sm, (it + STAGES - 1) % STAGES, m_base, n_base,
                       (it + STAGES - 1) * BK, tid);
        }
        asm volatile("cp.async.commit_group;" ::: "memory");

        __half* sA = sm + (it % STAGES) * STAGE_HALVES;
        __half* sB = sA + TILE_HALVES;

        #pragma unroll
        for (int kh = 0; kh < 4; ++kh) {
            uint32_t a[4][4];
            #pragma unroll
            for (int mt = 0; mt < 4; ++mt) {
                uint32_t ad = smem_u32(sA + (warp_m * 64 + mt * 16 + lrow) * SK
                                          + kh * 16 + lch * 8);
                ldsm_x4(a[mt], ad);
            }
            uint32_t b[2][4];
            #pragma unroll
            for (int nt = 0; nt < 2; ++nt) {
                uint32_t bd = smem_u32(sB + (warp_n * 32 + nt * 16 + lrow) * SK
                                          + kh * 16 + lch * 8);
                ldsm_x4(b[nt], bd);
            }
            #pragma unroll
            for (int mt = 0; mt < 4; ++mt) {
                #pragma unroll
                for (int nt = 0; nt < 2; ++nt) {
                    // n8 block 2*nt -> regs {b0, b2}; 2*nt+1 -> {b1, b3}
                    mma16816(acc[mt][2 * nt + 0], a[mt], b[nt][0], b[nt][2]);
                    mma16816(acc[mt][2 * nt + 1], a[mt], b[nt][1], b[nt][3]);
                }
            }
        }
    }

    // epilogue: out[token][col] = acc + b2[col]
    const int col0 = n_base + warp_n * 32;
    float bb[4][2];
    #pragma unroll
    for (int n8 = 0; n8 < 4; ++n8) {
        int c = col0 + n8 * 8 + (lane & 3) * 2;
        bb[n8][0] = __ldg(&b2[c]);
        bb[n8][1] = __ldg(&b2[c + 1]);
    }
    #pragma unroll
    for (int mt = 0; mt < 4; ++mt) {
        const int row0 = m_base + warp_m * 64 + mt * 16 + (lane >> 2);
        #pragma unroll
        for (int n8 = 0; n8 < 4; ++n8) {
            const int c = col0 + n8 * 8 + (lane & 3) * 2;
            float2 v0 = make_float2(acc[mt][n8][0] + bb[n8][0],
                                    acc[mt][n8][1] + bb[n8][1]);
            float2 v1 = make_float2(acc[mt][n8][2] + bb[n8][0],
                                    acc[mt][n8][3] + bb[n8][1]);
            *reinterpret_cast<float2*>(out + (size_t)row0 * EDIM + c) = v0;
            *reinterpret_cast<float2*>(out + (size_t)(row0 + 8) * EDIM + c) = v1;
        }
    }
}

// ---------------- launch ----------------
extern "C" void kernel_launch(void* const* d_in, const int* in_sizes, int n_in,
                              void* d_out, int out_size) {
    const float *x = nullptr, *W1 = nullptr, *b1 = nullptr, *W2 = nullptr, *b2 = nullptr;
    for (int i = 0; i < n_in; ++i) {
        const float* p = (const float*)d_in[i];
        int s = in_sizes[i];
        if (s == TOKENS * EDIM)      x = p;
        else if (s == FDIM * 10)     W1 = p;
        else if (s == EDIM * FDIM)   W2 = p;
        else if (s == 1024) {
            if (!b1) b1 = p; else b2 = p;
        }
        // s == 10 -> rz_theta: phases drop out of <Z>, unused
    }
    float* out = (float*)d_out;

    prep_kernel<<<1280, 256>>>(x, W1, b1, W2);

    cudaFuncSetAttribute(gemm_kernel, cudaFuncAttributeMaxDynamicSharedMemorySize,
                         GEMM_SMEM_BYTES);
    dim3 grid(EDIM / BN, TOKENS / BM);   // (8, 256); N-tiles innermost for A reuse
    gemm_kernel<<<grid, GTHREADS, GEMM_SMEM_BYTES>>>(b2, out);
}

// round 6
// speedup vs baseline: 1.0990x; 1.0176x over previous
#include <cuda_runtime.h>
#include <cuda_fp16.h>
#include <cstdint>
#include <cstddef>

// Problem dims
#define TOKENS 32768
#define EDIM   1024
#define FDIM   1024

// GEMM tiling: CTA 128x128x64, 4 warps (2x2), warp tile 64x64
#define BM 128
#define BN 128
#define BK 64
#define STAGES 3
#define KITERS (FDIM / BK)        // 16
#define GTHREADS 128              // 4 warps: 2 (M) x 2 (N)

// smem: padded row stride 72 halves (144B) -> conflict-free ldmatrix
#define SK 72
#define TILE_HALVES (128 * SK)                    // per operand per stage
#define STAGE_HALVES (2 * TILE_HALVES)            // A then B
#define GEMM_SMEM_BYTES (STAGES * STAGE_HALVES * 2)   // 110592 B

// ---------------- scratch (static device globals: allowed) ----------------
__device__ __half g_Hh[(size_t)TOKENS * FDIM];    // 64 MB
__device__ __half g_W2h[EDIM * FDIM];             // 2 MB

// ---------------- helpers ----------------
__device__ __forceinline__ uint32_t smem_u32(const void* p) {
    return (uint32_t)__cvta_generic_to_shared(p);
}
__device__ __forceinline__ void cp16(uint32_t dst, const __half* src) {
    asm volatile("cp.async.cg.shared.global [%0], [%1], 16;"
                 :: "r"(dst), "l"(__cvta_generic_to_global((const void*)src))
                 : "memory");
}
__device__ __forceinline__ void ldsm_x4(uint32_t* r, uint32_t addr) {
    asm volatile("ldmatrix.sync.aligned.m8n8.x4.shared.b16 {%0,%1,%2,%3}, [%4];"
                 : "=r"(r[0]), "=r"(r[1]), "=r"(r[2]), "=r"(r[3]) : "r"(addr));
}
__device__ __forceinline__ void mma16816(float* c, const uint32_t* a, uint32_t b0, uint32_t b1) {
    asm volatile(
        "mma.sync.aligned.m16n8k16.row.col.f32.f16.f16.f32 "
        "{%0,%1,%2,%3}, {%4,%5,%6,%7}, {%8,%9}, {%0,%1,%2,%3};"
        : "+f"(c[0]), "+f"(c[1]), "+f"(c[2]), "+f"(c[3])
        : "r"(a[0]), "r"(a[1]), "r"(a[2]), "r"(a[3]), "r"(b0), "r"(b1));
}

// ---------------- kernel 1: prep = {H build} U {W2 convert} ----------------
// blocks [0, 1024): H for 32 tokens each.  blocks [1024, 1280): W2 fp32->fp16.
__global__ void __launch_bounds__(256) prep_kernel(const float* __restrict__ x,
                                                   const float* __restrict__ W1,
                                                   const float* __restrict__ b1,
                                                   const float* __restrict__ W2) {
    if (blockIdx.x >= 1024) {
        int base = (blockIdx.x - 1024) * 4096 + threadIdx.x;
        #pragma unroll
        for (int i = 0; i < 16; ++i) {
            int idx = base + i * 256;
            g_W2h[idx] = __float2half_rn(W2[idx]);
        }
        return;
    }
    __shared__ float sW1T[10 * 1024];   // [q][f], f-major (float4-friendly)
    __shared__ float sb1[1024];
    const int tid = threadIdx.x;
    for (int i = tid; i < 10 * 1024; i += 256) {
        int f = i / 10, q = i % 10;
        sW1T[q * 1024 + f] = W1[i];
    }
    for (int i = tid; i < 1024; i += 256) sb1[i] = b1[i];
    __syncthreads();

    const int w = tid >> 5, l = tid & 31;
    const float4* sW1T4 = reinterpret_cast<const float4*>(sW1T);
    const float4* sb14  = reinterpret_cast<const float4*>(sb1);
    for (int t = 0; t < 4; ++t) {
        const int token = blockIdx.x * 32 + w * 4 + t;
        float zv = 0.0f;
        if (l < 10) zv = cosf(x[(size_t)token * EDIM + l]);
        float z[10];
        #pragma unroll
        for (int q = 0; q < 10; ++q) z[q] = __shfl_sync(0xffffffffu, zv, q);
        __half* dst = &g_Hh[(size_t)token * FDIM];
        // lane l handles 4 consecutive f per 128-chunk -> 8B coalesced stores
        #pragma unroll
        for (int c = 0; c < 8; ++c) {
            const int f4 = c * 32 + l;          // float4 index: f = 4*f4
            float4 acc = sb14[f4];
            #pragma unroll
            for (int q = 0; q < 10; ++q) {
                float4 wv = sW1T4[q * 256 + f4];
                acc.x = fmaf(z[q], wv.x, acc.x);
                acc.y = fmaf(z[q], wv.y, acc.y);
                acc.z = fmaf(z[q], wv.z, acc.z);
                acc.w = fmaf(z[q], wv.w, acc.w);
            }
            __half2 h0 = __floats2half2_rn(fmaxf(acc.x, 0.0f), fmaxf(acc.y, 0.0f));
            __half2 h1 = __floats2half2_rn(fmaxf(acc.z, 0.0f), fmaxf(acc.w, 0.0f));
            uint2 pk;
            pk.x = *reinterpret_cast<uint32_t*>(&h0);
            pk.y = *reinterpret_cast<uint32_t*>(&h1);
            *reinterpret_cast<uint2*>(dst + f4 * 4) = pk;
        }
    }
}

// ---------------- kernel 2: out = H @ W2^T + b2 (mma.sync pipeline) ----------------
__device__ __forceinline__ void load_stage(__half* sm, int stage, int m_base,
                                           int n_base, int k0, int tid) {
    __half* sA = sm + stage * STAGE_HALVES;
    __half* sB = sA + TILE_HALVES;
    // 1024 16B chunks each for A and B; 128 threads x 8 chunks each
    #pragma unroll
    for (int i = 0; i < 8; ++i) {
        int ch = tid + i * 128;
        int r = ch >> 3, c = ch & 7;
        uint32_t so = smem_u32(sA + r * SK + c * 8);
        cp16(so, &g_Hh[(size_t)(m_base + r) * FDIM + k0 + c * 8]);
    }
    #pragma unroll
    for (int i = 0; i < 8; ++i) {
        int ch = tid + i * 128;
        int r = ch >> 3, c = ch & 7;
        uint32_t so = smem_u32(sB + r * SK + c * 8);
        cp16(so, &g_W2h[(size_t)(n_base + r) * FDIM + k0 + c * 8]);
    }
}

__global__ void __launch_bounds__(GTHREADS, 2)
gemm_kernel(const float* __restrict__ b2, float* __restrict__ out) {
    extern __shared__ __half sm[];
    const int tid = threadIdx.x;
    const int wid = tid >> 5;
    const int lane = tid & 31;
    const int warp_m = wid & 1;        // 0..1  (64 rows each)
    const int warp_n = wid >> 1;       // 0..1  (64 cols each)
    const int m_base = blockIdx.y * BM;
    const int n_base = blockIdx.x * BN;

    float acc[4][8][4];                // [mt][n8][4]
    #pragma unroll
    for (int i = 0; i < 4; ++i)
        #pragma unroll
        for (int j = 0; j < 8; ++j)
            #pragma unroll
            for (int k = 0; k < 4; ++k) acc[i][j][k] = 0.0f;

    // prologue: fill STAGES-1 stages
    #pragma unroll
    for (int s = 0; s < STAGES - 1; ++s) {
        load_stage(sm, s, m_base, n_base, s * BK, tid);
        asm volatile("cp.async.commit_group;" ::: "memory");
    }

    // ldmatrix lane addressing: row = lane%16, chunk = lane/16
    const int lrow = lane & 15;
    const int lch  = lane >> 4;

    for (int it = 0; it < KITERS; ++it) {
        asm volatile("cp.async.wait_group %0;" :: "n"(STAGES - 2) : "memory");
        __syncthreads();

        if (it + STAGES - 1 < KITERS) {
            load_stage(sm, (it + STAGES - 1) % STAGES, m_base, n_base,
                       (it + STAGES - 1) * BK, tid);
        }
        asm volatile("cp.async.commit_group;" ::: "memory");

        __half* sA = sm + (it % STAGES) * STAGE_HALVES;
        __half* sB = sA + TILE_HALVES;

        #pragma unroll
        for (int kh = 0; kh < 4; ++kh) {
            uint32_t a[4][4];
            #pragma unroll
            for (int mt = 0; mt < 4; ++mt) {
                uint32_t ad = smem_u32(sA + (warp_m * 64 + mt * 16 + lrow) * SK
                                          + kh * 16 + lch * 8);
                ldsm_x4(a[mt], ad);
            }
            uint32_t b[4][4];
            #pragma unroll
            for (int nt = 0; nt < 4; ++nt) {
                uint32_t bd = smem_u32(sB + (warp_n * 64 + nt * 16 + lrow) * SK
                                          + kh * 16 + lch * 8);
                ldsm_x4(b[nt], bd);
            }
            #pragma unroll
            for (int mt = 0; mt < 4; ++mt) {
                #pragma unroll
                for (int nt = 0; nt < 4; ++nt) {
                    // n8 block 2*nt -> regs {b0, b2}; 2*nt+1 -> {b1, b3}
                    mma16816(acc[mt][2 * nt + 0], a[mt], b[nt][0], b[nt][2]);
                    mma16816(acc[mt][2 * nt + 1], a[mt], b[nt][1], b[nt][3]);
                }
            }
        }
    }

    // epilogue: out[token][col] = acc + b2[col]
    const int col0 = n_base + warp_n * 64;
    float bb[8][2];
    #pragma unroll
    for (int n8 = 0; n8 < 8; ++n8) {
        int c = col0 + n8 * 8 + (lane & 3) * 2;
        bb[n8][0] = __ldg(&b2[c]);
        bb[n8][1] = __ldg(&b2[c + 1]);
    }
    #pragma unroll
    for (int mt = 0; mt < 4; ++mt) {
        const int row0 = m_base + warp_m * 64 + mt * 16 + (lane >> 2);
        #pragma unroll
        for (int n8 = 0; n8 < 8; ++n8) {
            const int c = col0 + n8 * 8 + (lane & 3) * 2;
            float2 v0 = make_float2(acc[mt][n8][0] + bb[n8][0],
                                    acc[mt][n8][1] + bb[n8][1]);
            float2 v1 = make_float2(acc[mt][n8][2] + bb[n8][0],
                                    acc[mt][n8][3] + bb[n8][1]);
            *reinterpret_cast<float2*>(out + (size_t)row0 * EDIM + c) = v0;
            *reinterpret_cast<float2*>(out + (size_t)(row0 + 8) * EDIM + c) = v1;
        }
    }
}

// ---------------- launch ----------------
extern "C" void kernel_launch(void* const* d_in, const int* in_sizes, int n_in,
                              void* d_out, int out_size) {
    const float *x = nullptr, *W1 = nullptr, *b1 = nullptr, *W2 = nullptr, *b2 = nullptr;
    for (int i = 0; i < n_in; ++i) {
        const float* p = (const float*)d_in[i];
        int s = in_sizes[i];
        if (s == TOKENS * EDIM)      x = p;
        else if (s == FDIM * 10)     W1 = p;
        else if (s == EDIM * FDIM)   W2 = p;
        else if (s == 1024) {
            if (!b1) b1 = p; else b2 = p;
        }
        // s == 10 -> rz_theta: phases drop out of <Z>, unused
    }
    float* out = (float*)d_out;

    prep_kernel<<<1280, 256>>>(x, W1, b1, W2);

    cudaFuncSetAttribute(gemm_kernel, cudaFuncAttributeMaxDynamicSharedMemorySize,
                         GEMM_SMEM_BYTES);
    dim3 grid(EDIM / BN, TOKENS / BM);   // (8, 256); N-tiles innermost for A reuse
    gemm_kernel<<<grid, GTHREADS, GEMM_SMEM_BYTES>>>(b2, out);
}